// round 1
// baseline (speedup 1.0000x reference)
#include <cuda_runtime.h>
#include <cstdint>

// ---------------------------------------------------------------------------
// Problem constants (fixed by the dataset)
// ---------------------------------------------------------------------------
#define BATCH   8192
#define S_IN    4096
#define S_OUT   4096
#define HID     128
#define AR_N    7

// Scratch for hidden activations (allocation-free: __device__ globals)
__device__ float g_h1[BATCH * HID];
__device__ float g_h2[BATCH * HID];

// ---------------------------------------------------------------------------
// tf32 helpers
// ---------------------------------------------------------------------------
__device__ __forceinline__ uint32_t f2tf32(float x) {
    uint32_t u;
    asm("cvt.rna.tf32.f32 %0, %1;" : "=r"(u) : "f"(x));
    return u;
}

__device__ __forceinline__ void mma_tf32(float& d0, float& d1, float& d2, float& d3,
                                         uint32_t a0, uint32_t a1, uint32_t a2, uint32_t a3,
                                         uint32_t b0, uint32_t b1) {
    asm volatile(
        "mma.sync.aligned.m16n8k8.row.col.f32.tf32.tf32.f32 "
        "{%0,%1,%2,%3},{%4,%5,%6,%7},{%8,%9},{%0,%1,%2,%3};\n"
        : "+f"(d0), "+f"(d1), "+f"(d2), "+f"(d3)
        : "r"(a0), "r"(a1), "r"(a2), "r"(a3), "r"(b0), "r"(b1));
}

// ---------------------------------------------------------------------------
// Fused GEMM + bias + activation:
//   C[m][n] = act( sum_k A[m][k] * B[n][k] + bias[n] )
// A: M x K row-major, B: N x K row-major (i.e., weights (out,in)), C: M x N.
// Block tile 64x128, BK=32, 256 threads (8 warps as 2x4), warp tile 32x32,
// per-warp 2x4 mma(16x8) tiles. tf32 inputs, fp32 accumulate.
// ACT: 0 = relu, 1 = tanh
// ---------------------------------------------------------------------------
template <int ACT>
__global__ __launch_bounds__(256, 2)
void gemm_bias_act(const float* __restrict__ A,
                   const float* __restrict__ B,
                   const float* __restrict__ bias,
                   float* __restrict__ C,
                   int M, int N, int K) {
    __shared__ uint32_t As[64][36];   // stride 36 floats: 16B-aligned rows, conflict-free frags
    __shared__ uint32_t Bs[128][36];

    const int tid  = threadIdx.x;
    const int bm   = blockIdx.x * 64;
    const int bn   = blockIdx.y * 128;

    const int warp = tid >> 5;
    const int lane = tid & 31;
    const int wm   = warp & 1;    // 0..1
    const int wn   = warp >> 1;   // 0..3
    const int g    = lane >> 2;   // group id 0..7
    const int t    = lane & 3;    // thread-in-group 0..3

    float acc[2][4][4];
#pragma unroll
    for (int im = 0; im < 2; im++)
#pragma unroll
        for (int in_ = 0; in_ < 4; in_++)
#pragma unroll
            for (int j = 0; j < 4; j++) acc[im][in_][j] = 0.f;

    // ---- prologue: load tile 0 straight into smem (with tf32 convert) ----
    {
#pragma unroll
        for (int i = 0; i < 2; i++) {           // A: 64x32 = 512 float4
            int id = tid + i * 256;
            int r = id >> 3, c = (id & 7) * 4;
            float4 v = *reinterpret_cast<const float4*>(A + (size_t)(bm + r) * K + c);
            As[r][c + 0] = f2tf32(v.x); As[r][c + 1] = f2tf32(v.y);
            As[r][c + 2] = f2tf32(v.z); As[r][c + 3] = f2tf32(v.w);
        }
#pragma unroll
        for (int i = 0; i < 4; i++) {           // B: 128x32 = 1024 float4
            int id = tid + i * 256;
            int r = id >> 3, c = (id & 7) * 4;
            float4 v = *reinterpret_cast<const float4*>(B + (size_t)(bn + r) * K + c);
            Bs[r][c + 0] = f2tf32(v.x); Bs[r][c + 1] = f2tf32(v.y);
            Bs[r][c + 2] = f2tf32(v.z); Bs[r][c + 3] = f2tf32(v.w);
        }
    }
    __syncthreads();

    for (int kt = 0; kt < K; kt += 32) {
        // ---- prefetch next tile into registers ----
        float4 ra[2], rb[4];
        const bool has_next = (kt + 32) < K;
        if (has_next) {
            int kn = kt + 32;
#pragma unroll
            for (int i = 0; i < 2; i++) {
                int id = tid + i * 256;
                int r = id >> 3, c = (id & 7) * 4;
                ra[i] = *reinterpret_cast<const float4*>(A + (size_t)(bm + r) * K + kn + c);
            }
#pragma unroll
            for (int i = 0; i < 4; i++) {
                int id = tid + i * 256;
                int r = id >> 3, c = (id & 7) * 4;
                rb[i] = *reinterpret_cast<const float4*>(B + (size_t)(bn + r) * K + kn + c);
            }
        }

        // ---- compute on current smem tile ----
#pragma unroll
        for (int ks = 0; ks < 32; ks += 8) {
            uint32_t af[2][4];
#pragma unroll
            for (int im = 0; im < 2; im++) {
                int rb_ = wm * 32 + im * 16 + g;
                af[im][0] = As[rb_][ks + t];
                af[im][1] = As[rb_ + 8][ks + t];
                af[im][2] = As[rb_][ks + t + 4];
                af[im][3] = As[rb_ + 8][ks + t + 4];
            }
            uint32_t bf[4][2];
#pragma unroll
            for (int in_ = 0; in_ < 4; in_++) {
                int nb = wn * 32 + in_ * 8 + g;
                bf[in_][0] = Bs[nb][ks + t];
                bf[in_][1] = Bs[nb][ks + t + 4];
            }
#pragma unroll
            for (int im = 0; im < 2; im++)
#pragma unroll
                for (int in_ = 0; in_ < 4; in_++)
                    mma_tf32(acc[im][in_][0], acc[im][in_][1], acc[im][in_][2], acc[im][in_][3],
                             af[im][0], af[im][1], af[im][2], af[im][3],
                             bf[in_][0], bf[in_][1]);
        }

        if (has_next) {
            __syncthreads();
#pragma unroll
            for (int i = 0; i < 2; i++) {
                int id = tid + i * 256;
                int r = id >> 3, c = (id & 7) * 4;
                As[r][c + 0] = f2tf32(ra[i].x); As[r][c + 1] = f2tf32(ra[i].y);
                As[r][c + 2] = f2tf32(ra[i].z); As[r][c + 3] = f2tf32(ra[i].w);
            }
#pragma unroll
            for (int i = 0; i < 4; i++) {
                int id = tid + i * 256;
                int r = id >> 3, c = (id & 7) * 4;
                Bs[r][c + 0] = f2tf32(rb[i].x); Bs[r][c + 1] = f2tf32(rb[i].y);
                Bs[r][c + 2] = f2tf32(rb[i].z); Bs[r][c + 3] = f2tf32(rb[i].w);
            }
            __syncthreads();
        }
    }

    // ---- epilogue: bias + activation + store ----
#pragma unroll
    for (int im = 0; im < 2; im++) {
        int r0 = bm + wm * 32 + im * 16 + g;
#pragma unroll
        for (int in_ = 0; in_ < 4; in_++) {
            int c = bn + wn * 32 + in_ * 8 + 2 * t;
            float bv0 = bias[c], bv1 = bias[c + 1];
            float v00 = acc[im][in_][0] + bv0;
            float v01 = acc[im][in_][1] + bv1;
            float v10 = acc[im][in_][2] + bv0;
            float v11 = acc[im][in_][3] + bv1;
            if (ACT == 0) {
                v00 = fmaxf(v00, 0.f); v01 = fmaxf(v01, 0.f);
                v10 = fmaxf(v10, 0.f); v11 = fmaxf(v11, 0.f);
            } else {
                v00 = tanhf(v00); v01 = tanhf(v01);
                v10 = tanhf(v10); v11 = tanhf(v11);
            }
            *reinterpret_cast<float2*>(C + (size_t)r0 * N + c)       = make_float2(v00, v01);
            *reinterpret_cast<float2*>(C + (size_t)(r0 + 8) * N + c) = make_float2(v10, v11);
        }
    }
}

// ---------------------------------------------------------------------------
// AR(7) filter + accumulate into out:
//   y[t] = 0 for t < 7
//   y[t] = noise[t] + sum_i c[i] * y[t-1-i]  for t >= 7
//   out[b][t] += y[t]
// 64 rows per block (grid 128), t processed in chunks of 128 staged through
// SMEM for coalescing. 2 worker warps (one row per lane) carry the recurrence
// history in registers across chunks; all 8 warps do load & add phases.
// ---------------------------------------------------------------------------
__global__ __launch_bounds__(256, 1)
void ar_add_kernel(const float* __restrict__ noise,
                   const float* __restrict__ coef,
                   float* __restrict__ out) {
    __shared__ float ns[64][129];   // stride 129 -> conflict-free row-indexed access

    const int tid = threadIdx.x;
    const int r0  = blockIdx.x * 64;

    const float c0 = coef[0], c1 = coef[1], c2 = coef[2], c3 = coef[3],
                c4 = coef[4], c5 = coef[5], c6 = coef[6];

    // recurrence history (only meaningful for tid < 64): h0 = y[t-1] ... h6 = y[t-7]
    float h0 = 0.f, h1 = 0.f, h2 = 0.f, h3 = 0.f, h4 = 0.f, h5 = 0.f, h6 = 0.f;

    for (int ch = 0; ch < S_OUT / 128; ch++) {
        const int t0 = ch * 128;

        // ---- load noise chunk, coalesced: 64 rows x 32 float4 = 2048 f4 ----
#pragma unroll
        for (int i = 0; i < 8; i++) {
            int id = tid + i * 256;
            int r = id >> 5;              // 0..63
            int c = (id & 31) * 4;        // 0..124
            float4 v = *reinterpret_cast<const float4*>(
                noise + (size_t)(r0 + r) * S_OUT + t0 + c);
            ns[r][c + 0] = v.x; ns[r][c + 1] = v.y;
            ns[r][c + 2] = v.z; ns[r][c + 3] = v.w;
        }
        __syncthreads();

        // ---- recurrence: 2 worker warps, one row per lane ----
        if (tid < 64) {
            const int row = tid;
            int tl = 0;
            if (ch == 0) {
                for (; tl < AR_N; tl++) ns[row][tl] = 0.f;   // zeros head
            }
#pragma unroll 8
            for (; tl < 128; tl++) {
                float y = ns[row][tl];
                y = fmaf(c0, h0, y); y = fmaf(c1, h1, y); y = fmaf(c2, h2, y);
                y = fmaf(c3, h3, y); y = fmaf(c4, h4, y); y = fmaf(c5, h5, y);
                y = fmaf(c6, h6, y);
                ns[row][tl] = y;
                h6 = h5; h5 = h4; h4 = h3; h3 = h2; h2 = h1; h1 = h0; h0 = y;
            }
        }
        __syncthreads();

        // ---- out += y, coalesced r/m/w ----
#pragma unroll
        for (int i = 0; i < 8; i++) {
            int id = tid + i * 256;
            int r = id >> 5;
            int c = (id & 31) * 4;
            size_t o = (size_t)(r0 + r) * S_OUT + t0 + c;
            float4 v = *reinterpret_cast<float4*>(out + o);
            v.x += ns[r][c + 0]; v.y += ns[r][c + 1];
            v.z += ns[r][c + 2]; v.w += ns[r][c + 3];
            *reinterpret_cast<float4*>(out + o) = v;
        }
        __syncthreads();
    }
}

// ---------------------------------------------------------------------------
// Launch
// Inputs (metadata order): x, noise, W1, b1, W2, b2, W3, b3, ar_coef
// ---------------------------------------------------------------------------
extern "C" void kernel_launch(void* const* d_in, const int* in_sizes, int n_in,
                              void* d_out, int out_size) {
    const float* x     = (const float*)d_in[0];
    const float* noise = (const float*)d_in[1];
    const float* W1    = (const float*)d_in[2];
    const float* b1    = (const float*)d_in[3];
    const float* W2    = (const float*)d_in[4];
    const float* b2    = (const float*)d_in[5];
    const float* W3    = (const float*)d_in[6];
    const float* b3    = (const float*)d_in[7];
    const float* coef  = (const float*)d_in[8];
    float* out = (float*)d_out;

    float* h1 = nullptr;
    float* h2 = nullptr;
    cudaGetSymbolAddress((void**)&h1, g_h1);
    cudaGetSymbolAddress((void**)&h2, g_h2);

    // h1 = relu(x @ W1^T + b1)          M=8192, N=128, K=4096
    gemm_bias_act<0><<<dim3(BATCH / 64, HID / 128), 256>>>(x, W1, b1, h1, BATCH, HID, S_IN);
    // h2 = relu(h1 @ W2^T + b2)         M=8192, N=128, K=128
    gemm_bias_act<0><<<dim3(BATCH / 64, HID / 128), 256>>>(h1, W2, b2, h2, BATCH, HID, HID);
    // out = tanh(h2 @ W3^T + b3)        M=8192, N=4096, K=128
    gemm_bias_act<1><<<dim3(BATCH / 64, S_OUT / 128), 256>>>(h2, W3, b3, out, BATCH, S_OUT, HID);
    // out += ar_filter(noise, coef)
    ar_add_kernel<<<BATCH / 64, 256>>>(noise, coef, out);
}

// round 2
// speedup vs baseline: 1.0013x; 1.0013x over previous
#include <cuda_runtime.h>
#include <cstdint>

// ---------------------------------------------------------------------------
// Problem constants (fixed by the dataset)
// ---------------------------------------------------------------------------
#define BATCH   8192
#define S_IN    4096
#define S_OUT   4096
#define HID     128
#define AR_N    7

// Scratch for hidden activations (allocation-free: __device__ globals)
__device__ float g_h1[BATCH * HID];
__device__ float g_h2[BATCH * HID];

// ---------------------------------------------------------------------------
// tf32 helpers
// ---------------------------------------------------------------------------
__device__ __forceinline__ uint32_t f2tf32(float x) {
    uint32_t u;
    asm("cvt.rna.tf32.f32 %0, %1;" : "=r"(u) : "f"(x));
    return u;
}

__device__ __forceinline__ void mma_tf32(float& d0, float& d1, float& d2, float& d3,
                                         uint32_t a0, uint32_t a1, uint32_t a2, uint32_t a3,
                                         uint32_t b0, uint32_t b1) {
    asm volatile(
        "mma.sync.aligned.m16n8k8.row.col.f32.tf32.tf32.f32 "
        "{%0,%1,%2,%3},{%4,%5,%6,%7},{%8,%9},{%0,%1,%2,%3};\n"
        : "+f"(d0), "+f"(d1), "+f"(d2), "+f"(d3)
        : "r"(a0), "r"(a1), "r"(a2), "r"(a3), "r"(b0), "r"(b1));
}

// ---------------------------------------------------------------------------
// Fused GEMM + bias + activation:
//   C[m][n] = act( sum_k A[m][k] * B[n][k] + bias[n] )
// A: M x K row-major, B: N x K row-major (i.e., weights (out,in)), C: M x N.
// Block tile 64x128, BK=32, 256 threads (8 warps as 2x4), warp tile 32x32,
// per-warp 2x4 mma(16x8) tiles. tf32 inputs, fp32 accumulate.
// ACT: 0 = relu, 1 = tanh
// ---------------------------------------------------------------------------
template <int ACT>
__global__ __launch_bounds__(256, 2)
void gemm_bias_act(const float* __restrict__ A,
                   const float* __restrict__ B,
                   const float* __restrict__ bias,
                   float* __restrict__ C,
                   int M, int N, int K) {
    __shared__ uint32_t As[64][36];   // stride 36 floats: 16B-aligned rows, conflict-free frags
    __shared__ uint32_t Bs[128][36];

    const int tid  = threadIdx.x;
    const int bm   = blockIdx.x * 64;
    const int bn   = blockIdx.y * 128;

    const int warp = tid >> 5;
    const int lane = tid & 31;
    const int wm   = warp & 1;    // 0..1
    const int wn   = warp >> 1;   // 0..3
    const int g    = lane >> 2;   // group id 0..7
    const int t    = lane & 3;    // thread-in-group 0..3

    float acc[2][4][4];
#pragma unroll
    for (int im = 0; im < 2; im++)
#pragma unroll
        for (int in_ = 0; in_ < 4; in_++)
#pragma unroll
            for (int j = 0; j < 4; j++) acc[im][in_][j] = 0.f;

    // ---- prologue: load tile 0 straight into smem (with tf32 convert) ----
    {
#pragma unroll
        for (int i = 0; i < 2; i++) {           // A: 64x32 = 512 float4
            int id = tid + i * 256;
            int r = id >> 3, c = (id & 7) * 4;
            float4 v = *reinterpret_cast<const float4*>(A + (size_t)(bm + r) * K + c);
            As[r][c + 0] = f2tf32(v.x); As[r][c + 1] = f2tf32(v.y);
            As[r][c + 2] = f2tf32(v.z); As[r][c + 3] = f2tf32(v.w);
        }
#pragma unroll
        for (int i = 0; i < 4; i++) {           // B: 128x32 = 1024 float4
            int id = tid + i * 256;
            int r = id >> 3, c = (id & 7) * 4;
            float4 v = *reinterpret_cast<const float4*>(B + (size_t)(bn + r) * K + c);
            Bs[r][c + 0] = f2tf32(v.x); Bs[r][c + 1] = f2tf32(v.y);
            Bs[r][c + 2] = f2tf32(v.z); Bs[r][c + 3] = f2tf32(v.w);
        }
    }
    __syncthreads();

    for (int kt = 0; kt < K; kt += 32) {
        // ---- prefetch next tile into registers ----
        float4 ra[2], rb[4];
        const bool has_next = (kt + 32) < K;
        if (has_next) {
            int kn = kt + 32;
#pragma unroll
            for (int i = 0; i < 2; i++) {
                int id = tid + i * 256;
                int r = id >> 3, c = (id & 7) * 4;
                ra[i] = *reinterpret_cast<const float4*>(A + (size_t)(bm + r) * K + kn + c);
            }
#pragma unroll
            for (int i = 0; i < 4; i++) {
                int id = tid + i * 256;
                int r = id >> 3, c = (id & 7) * 4;
                rb[i] = *reinterpret_cast<const float4*>(B + (size_t)(bn + r) * K + kn + c);
            }
        }

        // ---- compute on current smem tile ----
#pragma unroll
        for (int ks = 0; ks < 32; ks += 8) {
            uint32_t af[2][4];
#pragma unroll
            for (int im = 0; im < 2; im++) {
                int rb_ = wm * 32 + im * 16 + g;
                af[im][0] = As[rb_][ks + t];
                af[im][1] = As[rb_ + 8][ks + t];
                af[im][2] = As[rb_][ks + t + 4];
                af[im][3] = As[rb_ + 8][ks + t + 4];
            }
            uint32_t bf[4][2];
#pragma unroll
            for (int in_ = 0; in_ < 4; in_++) {
                int nb = wn * 32 + in_ * 8 + g;
                bf[in_][0] = Bs[nb][ks + t];
                bf[in_][1] = Bs[nb][ks + t + 4];
            }
#pragma unroll
            for (int im = 0; im < 2; im++)
#pragma unroll
                for (int in_ = 0; in_ < 4; in_++)
                    mma_tf32(acc[im][in_][0], acc[im][in_][1], acc[im][in_][2], acc[im][in_][3],
                             af[im][0], af[im][1], af[im][2], af[im][3],
                             bf[in_][0], bf[in_][1]);
        }

        if (has_next) {
            __syncthreads();
#pragma unroll
            for (int i = 0; i < 2; i++) {
                int id = tid + i * 256;
                int r = id >> 3, c = (id & 7) * 4;
                As[r][c + 0] = f2tf32(ra[i].x); As[r][c + 1] = f2tf32(ra[i].y);
                As[r][c + 2] = f2tf32(ra[i].z); As[r][c + 3] = f2tf32(ra[i].w);
            }
#pragma unroll
            for (int i = 0; i < 4; i++) {
                int id = tid + i * 256;
                int r = id >> 3, c = (id & 7) * 4;
                Bs[r][c + 0] = f2tf32(rb[i].x); Bs[r][c + 1] = f2tf32(rb[i].y);
                Bs[r][c + 2] = f2tf32(rb[i].z); Bs[r][c + 3] = f2tf32(rb[i].w);
            }
            __syncthreads();
        }
    }

    // ---- epilogue: bias + activation + store ----
#pragma unroll
    for (int im = 0; im < 2; im++) {
        int r0 = bm + wm * 32 + im * 16 + g;
#pragma unroll
        for (int in_ = 0; in_ < 4; in_++) {
            int c = bn + wn * 32 + in_ * 8 + 2 * t;
            float bv0 = bias[c], bv1 = bias[c + 1];
            float v00 = acc[im][in_][0] + bv0;
            float v01 = acc[im][in_][1] + bv1;
            float v10 = acc[im][in_][2] + bv0;
            float v11 = acc[im][in_][3] + bv1;
            if (ACT == 0) {
                v00 = fmaxf(v00, 0.f); v01 = fmaxf(v01, 0.f);
                v10 = fmaxf(v10, 0.f); v11 = fmaxf(v11, 0.f);
            } else {
                v00 = tanhf(v00); v01 = tanhf(v01);
                v10 = tanhf(v10); v11 = tanhf(v11);
            }
            *reinterpret_cast<float2*>(C + (size_t)r0 * N + c)       = make_float2(v00, v01);
            *reinterpret_cast<float2*>(C + (size_t)(r0 + 8) * N + c) = make_float2(v10, v11);
        }
    }
}

// ---------------------------------------------------------------------------
// AR(7) filter + accumulate into out:
//   y[t] = 0 for t < 7
//   y[t] = noise[t] + sum_i c[i] * y[t-1-i]  for t >= 7
//   out[b][t] += y[t]
// 64 rows per block (grid 128), t processed in chunks of 128 staged through
// SMEM for coalescing. 2 worker warps (one row per lane) carry the recurrence
// history in registers across chunks; all 8 warps do load & add phases.
// ---------------------------------------------------------------------------
__global__ __launch_bounds__(256, 1)
void ar_add_kernel(const float* __restrict__ noise,
                   const float* __restrict__ coef,
                   float* __restrict__ out) {
    __shared__ float ns[64][129];   // stride 129 -> conflict-free row-indexed access

    const int tid = threadIdx.x;
    const int r0  = blockIdx.x * 64;

    const float c0 = coef[0], c1 = coef[1], c2 = coef[2], c3 = coef[3],
                c4 = coef[4], c5 = coef[5], c6 = coef[6];

    // recurrence history (only meaningful for tid < 64): h0 = y[t-1] ... h6 = y[t-7]
    float h0 = 0.f, h1 = 0.f, h2 = 0.f, h3 = 0.f, h4 = 0.f, h5 = 0.f, h6 = 0.f;

    for (int ch = 0; ch < S_OUT / 128; ch++) {
        const int t0 = ch * 128;

        // ---- load noise chunk, coalesced: 64 rows x 32 float4 = 2048 f4 ----
#pragma unroll
        for (int i = 0; i < 8; i++) {
            int id = tid + i * 256;
            int r = id >> 5;              // 0..63
            int c = (id & 31) * 4;        // 0..124
            float4 v = *reinterpret_cast<const float4*>(
                noise + (size_t)(r0 + r) * S_OUT + t0 + c);
            ns[r][c + 0] = v.x; ns[r][c + 1] = v.y;
            ns[r][c + 2] = v.z; ns[r][c + 3] = v.w;
        }
        __syncthreads();

        // ---- recurrence: 2 worker warps, one row per lane ----
        if (tid < 64) {
            const int row = tid;
            int tl = 0;
            if (ch == 0) {
                for (; tl < AR_N; tl++) ns[row][tl] = 0.f;   // zeros head
            }
#pragma unroll 8
            for (; tl < 128; tl++) {
                float y = ns[row][tl];
                y = fmaf(c0, h0, y); y = fmaf(c1, h1, y); y = fmaf(c2, h2, y);
                y = fmaf(c3, h3, y); y = fmaf(c4, h4, y); y = fmaf(c5, h5, y);
                y = fmaf(c6, h6, y);
                ns[row][tl] = y;
                h6 = h5; h5 = h4; h4 = h3; h3 = h2; h2 = h1; h1 = h0; h0 = y;
            }
        }
        __syncthreads();

        // ---- out += y, coalesced r/m/w ----
#pragma unroll
        for (int i = 0; i < 8; i++) {
            int id = tid + i * 256;
            int r = id >> 5;
            int c = (id & 31) * 4;
            size_t o = (size_t)(r0 + r) * S_OUT + t0 + c;
            float4 v = *reinterpret_cast<float4*>(out + o);
            v.x += ns[r][c + 0]; v.y += ns[r][c + 1];
            v.z += ns[r][c + 2]; v.w += ns[r][c + 3];
            *reinterpret_cast<float4*>(out + o) = v;
        }
        __syncthreads();
    }
}

// ---------------------------------------------------------------------------
// Launch
// Inputs (metadata order): x, noise, W1, b1, W2, b2, W3, b3, ar_coef
// ---------------------------------------------------------------------------
extern "C" void kernel_launch(void* const* d_in, const int* in_sizes, int n_in,
                              void* d_out, int out_size) {
    const float* x     = (const float*)d_in[0];
    const float* noise = (const float*)d_in[1];
    const float* W1    = (const float*)d_in[2];
    const float* b1    = (const float*)d_in[3];
    const float* W2    = (const float*)d_in[4];
    const float* b2    = (const float*)d_in[5];
    const float* W3    = (const float*)d_in[6];
    const float* b3    = (const float*)d_in[7];
    const float* coef  = (const float*)d_in[8];
    float* out = (float*)d_out;

    float* h1 = nullptr;
    float* h2 = nullptr;
    cudaGetSymbolAddress((void**)&h1, g_h1);
    cudaGetSymbolAddress((void**)&h2, g_h2);

    // h1 = relu(x @ W1^T + b1)          M=8192, N=128, K=4096
    gemm_bias_act<0><<<dim3(BATCH / 64, HID / 128), 256>>>(x, W1, b1, h1, BATCH, HID, S_IN);
    // h2 = relu(h1 @ W2^T + b2)         M=8192, N=128, K=128
    gemm_bias_act<0><<<dim3(BATCH / 64, HID / 128), 256>>>(h1, W2, b2, h2, BATCH, HID, HID);
    // out = tanh(h2 @ W3^T + b3)        M=8192, N=4096, K=128
    gemm_bias_act<1><<<dim3(BATCH / 64, S_OUT / 128), 256>>>(h2, W3, b3, out, BATCH, S_OUT, HID);
    // out += ar_filter(noise, coef)
    ar_add_kernel<<<BATCH / 64, 256>>>(noise, coef, out);
}